// round 1
// baseline (speedup 1.0000x reference)
#include <cuda_runtime.h>
#include <math.h>
#include <stdint.h>

// Problem constants
#define BB 2
#define TT 2048
#define CC 2048
#define NH 16
#define NKV 4
#define HD 128
#define GG 4
#define WINDOW 1024
#define SOFTCAP 50.0f

#define MROWS (BB*TT)   // 4096

// Scratch (no allocations allowed): ~84 MB of device globals
__device__ float g_Q[MROWS * (NH*HD)];    // 4096 x 2048
__device__ float g_K[MROWS * (NKV*HD)];   // 4096 x 512
__device__ float g_V[MROWS * (NKV*HD)];   // 4096 x 512
__device__ float g_E[MROWS * (NH*HD)];    // 4096 x 2048

// ---------------------------------------------------------------------------
// Tiled SGEMM: C[M,N] = A[M,K] * B[K,N], all row-major fp32.
// BM=BN=64, BK=16, 16x16 threads, 4x4 micro-tile per thread.
// All dims here are multiples of the tile sizes (4096, 2048/512, 2048).
// ---------------------------------------------------------------------------
__global__ __launch_bounds__(256) void sgemm_kernel(
    const float* __restrict__ A, const float* __restrict__ B,
    float* __restrict__ C, int M, int N, int Kd)
{
    __shared__ float As[16][68];
    __shared__ float Bs[16][68];

    const int tx = threadIdx.x;          // 0..15
    const int ty = threadIdx.y;          // 0..15
    const int tid = ty * 16 + tx;        // 0..255

    const int blockRow = blockIdx.y * 64;
    const int blockCol = blockIdx.x * 64;

    // A-tile loader: 64 rows x 16 cols = 256 float4 (one per thread)
    const int arow  = tid >> 2;          // 0..63
    const int acol4 = tid & 3;           // 0..3  (float4 index within 16)
    // B-tile loader: 16 rows x 64 cols = 256 float4 (one per thread)
    const int brow  = tid >> 4;          // 0..15
    const int bcol4 = tid & 15;          // 0..15 (float4 index within 64)

    float acc[4][4];
    #pragma unroll
    for (int i = 0; i < 4; i++)
        #pragma unroll
        for (int j = 0; j < 4; j++) acc[i][j] = 0.0f;

    for (int k0 = 0; k0 < Kd; k0 += 16) {
        float4 a = *(const float4*)(A + (size_t)(blockRow + arow) * Kd + k0 + acol4 * 4);
        As[acol4*4 + 0][arow] = a.x;
        As[acol4*4 + 1][arow] = a.y;
        As[acol4*4 + 2][arow] = a.z;
        As[acol4*4 + 3][arow] = a.w;

        float4 b = *(const float4*)(B + (size_t)(k0 + brow) * N + blockCol + bcol4 * 4);
        Bs[brow][bcol4*4 + 0] = b.x;
        Bs[brow][bcol4*4 + 1] = b.y;
        Bs[brow][bcol4*4 + 2] = b.z;
        Bs[brow][bcol4*4 + 3] = b.w;

        __syncthreads();

        #pragma unroll
        for (int kk = 0; kk < 16; kk++) {
            float ar[4], br[4];
            #pragma unroll
            for (int i = 0; i < 4; i++) ar[i] = As[kk][ty*4 + i];
            #pragma unroll
            for (int j = 0; j < 4; j++) br[j] = Bs[kk][tx*4 + j];
            #pragma unroll
            for (int i = 0; i < 4; i++)
                #pragma unroll
                for (int j = 0; j < 4; j++)
                    acc[i][j] = fmaf(ar[i], br[j], acc[i][j]);
        }
        __syncthreads();
    }

    #pragma unroll
    for (int i = 0; i < 4; i++) {
        float* crow = C + (size_t)(blockRow + ty*4 + i) * N + blockCol + tx*4;
        #pragma unroll
        for (int j = 0; j < 4; j++) crow[j] = acc[i][j];
    }
}

// ---------------------------------------------------------------------------
// RoPE: in-place over data[row, head, 128]. grid = rows*nheads, block = 64.
// Pair (i, i+64) share angle t * theta^{-2i/128}.
// ---------------------------------------------------------------------------
__global__ void rope_kernel(float* data, int nheads)
{
    const int idx = blockIdx.x;
    const int h   = idx % nheads;
    const int row = idx / nheads;        // b*T + t
    const int t   = row % TT;

    float* p = data + (size_t)row * nheads * HD + h * HD;
    const int i = threadIdx.x;           // 0..63

    const float inv = expf(-(2.0f * i / 128.0f) * logf(10000.0f));
    const float a = (float)t * inv;
    const float c = cosf(a), s = sinf(a);

    const float x1 = p[i];
    const float x2 = p[i + 64];
    p[i]      = x1 * c - x2 * s;
    p[i + 64] = x2 * c + x1 * s;
}

// ---------------------------------------------------------------------------
// Attention: one 128-thread block per (b, t, head).
// Sliding causal window: keys s in [max(0, t-1024), t].
// logits = 50*tanh((q_scaled . k)/50); softmax; PV.
// ---------------------------------------------------------------------------
__global__ __launch_bounds__(128) void attn_kernel(
    const float* __restrict__ Q, const float* __restrict__ K,
    const float* __restrict__ V, float* __restrict__ E)
{
    __shared__ float sq[HD];
    __shared__ float sl[WINDOW + 8];     // up to 1025 logits / probs
    __shared__ float sred[128];

    const int tid = threadIdx.x;
    const int idx = blockIdx.x;
    const int hh  = idx % NH;
    const int t   = (idx / NH) % TT;
    const int b   = idx / (NH * TT);
    const int kv  = hh >> 2;             // hh / G

    const float scale = 0.08838834764831845f;  // 128^-0.5

    // load q (scaled)
    sq[tid] = Q[((size_t)(b*TT + t)) * (NH*HD) + hh * HD + tid] * scale;
    __syncthreads();

    int s0 = t - WINDOW; if (s0 < 0) s0 = 0;
    const int count = t - s0 + 1;        // <= 1025

    const int warp = tid >> 5;
    const int lane = tid & 31;
    const float4 qv = ((const float4*)sq)[lane];

    // Phase 1: logits — warp per key, lane covers 4 dims, shuffle-reduce
    for (int si = warp; si < count; si += 4) {
        const size_t koff = ((size_t)(b*TT + s0 + si)) * (NKV*HD) + kv * HD;
        const float4 kk = *(const float4*)(K + koff + lane * 4);
        float d = qv.x*kk.x + qv.y*kk.y + qv.z*kk.z + qv.w*kk.w;
        #pragma unroll
        for (int o = 16; o > 0; o >>= 1) d += __shfl_xor_sync(0xffffffffu, d, o);
        if (lane == 0) sl[si] = SOFTCAP * tanhf(d * (1.0f / SOFTCAP));
    }
    __syncthreads();

    // Phase 2: softmax
    float m = -INFINITY;
    for (int si = tid; si < count; si += 128) m = fmaxf(m, sl[si]);
    sred[tid] = m;
    __syncthreads();
    #pragma unroll
    for (int s = 64; s > 0; s >>= 1) {
        if (tid < s) sred[tid] = fmaxf(sred[tid], sred[tid + s]);
        __syncthreads();
    }
    m = sred[0];
    __syncthreads();

    float sum = 0.0f;
    for (int si = tid; si < count; si += 128) {
        const float e = __expf(sl[si] - m);
        sl[si] = e;
        sum += e;
    }
    sred[tid] = sum;
    __syncthreads();
    #pragma unroll
    for (int s = 64; s > 0; s >>= 1) {
        if (tid < s) sred[tid] += sred[tid + s];
        __syncthreads();
    }
    const float inv = 1.0f / sred[0];
    __syncthreads();

    // Phase 3: PV — thread per dim, coalesced V reads, 4-way unroll
    const float* vbase = V + ((size_t)(b*TT + s0)) * (NKV*HD) + kv * HD + tid;
    float a0 = 0.0f, a1 = 0.0f, a2 = 0.0f, a3 = 0.0f;
    int si = 0;
    for (; si + 4 <= count; si += 4) {
        a0 = fmaf(sl[si + 0], vbase[(size_t)(si + 0) * (NKV*HD)], a0);
        a1 = fmaf(sl[si + 1], vbase[(size_t)(si + 1) * (NKV*HD)], a1);
        a2 = fmaf(sl[si + 2], vbase[(size_t)(si + 2) * (NKV*HD)], a2);
        a3 = fmaf(sl[si + 3], vbase[(size_t)(si + 3) * (NKV*HD)], a3);
    }
    for (; si < count; si++)
        a0 = fmaf(sl[si], vbase[(size_t)si * (NKV*HD)], a0);

    E[((size_t)(b*TT + t)) * (NH*HD) + hh * HD + tid] = (a0 + a1 + a2 + a3) * inv;
}

// ---------------------------------------------------------------------------
// Launch
// ---------------------------------------------------------------------------
extern "C" void kernel_launch(void* const* d_in, const int* in_sizes, int n_in,
                              void* d_out, int out_size)
{
    const float* x  = (const float*)d_in[0];  // [2,2048,2048]
    const float* qk = (const float*)d_in[1];  // [2048,2048]
    const float* kk = (const float*)d_in[2];  // [2048,512]
    const float* vk = (const float*)d_in[3];  // [2048,512]
    const float* ok = (const float*)d_in[4];  // [2048,2048]
    float* out = (float*)d_out;               // [2,2048,2048]

    float *Q, *K, *V, *E;
    cudaGetSymbolAddress((void**)&Q, g_Q);
    cudaGetSymbolAddress((void**)&K, g_K);
    cudaGetSymbolAddress((void**)&V, g_V);
    cudaGetSymbolAddress((void**)&E, g_E);

    dim3 tb(16, 16);

    // QKV projections
    sgemm_kernel<<<dim3((NH*HD)/64,  MROWS/64), tb>>>(x, qk, Q, MROWS, NH*HD,  CC);
    sgemm_kernel<<<dim3((NKV*HD)/64, MROWS/64), tb>>>(x, kk, K, MROWS, NKV*HD, CC);
    sgemm_kernel<<<dim3((NKV*HD)/64, MROWS/64), tb>>>(x, vk, V, MROWS, NKV*HD, CC);

    // RoPE
    rope_kernel<<<MROWS * NH,  64>>>(Q, NH);
    rope_kernel<<<MROWS * NKV, 64>>>(K, NKV);

    // Attention
    attn_kernel<<<BB * TT * NH, 128>>>(Q, K, V, E);

    // Output projection
    sgemm_kernel<<<dim3(CC/64, MROWS/64), tb>>>(E, ok, out, MROWS, CC, CC);
}

// round 2
// speedup vs baseline: 1.0548x; 1.0548x over previous
#include <cuda_runtime.h>
#include <math.h>
#include <stdint.h>

#define BB 2
#define TT 2048
#define CC 2048
#define NH 16
#define NKV 4
#define HD 128
#define GG 4
#define WINDOW 1024
#define SOFTCAP 50.0f

#define MROWS (BB*TT)   // 4096

__device__ float g_Q[MROWS * (NH*HD)];    // 4096 x 2048
__device__ float g_K[MROWS * (NKV*HD)];   // 4096 x 512
__device__ float g_V[MROWS * (NKV*HD)];   // 4096 x 512
__device__ float g_E[MROWS * (NH*HD)];    // 4096 x 2048

// ---------------------------------------------------------------------------
// SGEMM: C[M,N] = A[M,K]*B[K,N] row-major fp32.
// 128x128 block tile, BK=8, 256 threads, 8x8 micro-tile, register prefetch.
// ---------------------------------------------------------------------------
__global__ __launch_bounds__(256) void sgemm128(
    const float* __restrict__ A, const float* __restrict__ B,
    float* __restrict__ C, int M, int N, int Kd)
{
    __shared__ float As[8][132];
    __shared__ float Bs[8][132];

    const int tid = threadIdx.x;
    const int tx = tid & 15;             // 0..15
    const int ty = tid >> 4;             // 0..15

    const int row0 = blockIdx.y * 128;
    const int col0 = blockIdx.x * 128;

    // A loader: 128 rows x 8 cols -> 256 float4 (one per thread)
    const int arow = tid >> 1;           // 0..127
    const int acol = (tid & 1) * 4;      // 0 or 4
    // B loader: 8 rows x 128 cols -> 256 float4
    const int brow = tid >> 5;           // 0..7
    const int bcol = (tid & 31) * 4;     // 0..124

    const float* Aptr = A + (size_t)(row0 + arow) * Kd + acol;
    const float* Bptr = B + (size_t)brow * N + col0 + bcol;

    float acc[8][8];
    #pragma unroll
    for (int i = 0; i < 8; i++)
        #pragma unroll
        for (int j = 0; j < 8; j++) acc[i][j] = 0.0f;

    float4 a = *(const float4*)Aptr;
    float4 b = *(const float4*)Bptr;

    const int nIter = Kd / 8;
    for (int it = 0; it < nIter; it++) {
        As[acol + 0][arow] = a.x;
        As[acol + 1][arow] = a.y;
        As[acol + 2][arow] = a.z;
        As[acol + 3][arow] = a.w;
        *(float4*)&Bs[brow][bcol] = b;
        __syncthreads();

        if (it + 1 < nIter) {
            a = *(const float4*)(Aptr + (it + 1) * 8);
            b = *(const float4*)(Bptr + (size_t)(it + 1) * 8 * N);
        }

        #pragma unroll
        for (int kk = 0; kk < 8; kk++) {
            float ar[8], br[8];
            *(float4*)&ar[0] = *(const float4*)&As[kk][ty * 8];
            *(float4*)&ar[4] = *(const float4*)&As[kk][ty * 8 + 4];
            *(float4*)&br[0] = *(const float4*)&Bs[kk][tx * 8];
            *(float4*)&br[4] = *(const float4*)&Bs[kk][tx * 8 + 4];
            #pragma unroll
            for (int i = 0; i < 8; i++)
                #pragma unroll
                for (int j = 0; j < 8; j++)
                    acc[i][j] = fmaf(ar[i], br[j], acc[i][j]);
        }
        __syncthreads();
    }

    #pragma unroll
    for (int i = 0; i < 8; i++) {
        float* crow = C + (size_t)(row0 + ty * 8 + i) * N + col0 + tx * 8;
        *(float4*)crow       = *(float4*)&acc[i][0];
        *(float4*)(crow + 4) = *(float4*)&acc[i][4];
    }
}

// ---------------------------------------------------------------------------
// RoPE
// ---------------------------------------------------------------------------
__global__ void rope_kernel(float* data, int nheads)
{
    const int idx = blockIdx.x;
    const int h   = idx % nheads;
    const int row = idx / nheads;
    const int t   = row % TT;

    float* p = data + (size_t)row * nheads * HD + h * HD;
    const int i = threadIdx.x;           // 0..63

    const float inv = expf(-(2.0f * i / 128.0f) * logf(10000.0f));
    const float a = (float)t * inv;
    const float c = cosf(a), s = sinf(a);

    const float x1 = p[i];
    const float x2 = p[i + 64];
    p[i]      = x1 * c - x2 * s;
    p[i + 64] = x2 * c + x1 * s;
}

// ---------------------------------------------------------------------------
// Attention: one block per (b, t, kv-group). 256 threads.
// The 4 GQA heads in the group share every K and V load.
// ---------------------------------------------------------------------------
__global__ __launch_bounds__(256) void attn_kernel(
    const float* __restrict__ Q, const float* __restrict__ K,
    const float* __restrict__ V, float* __restrict__ E)
{
    __shared__ float sq[GG][HD];
    __shared__ float sl[GG][WINDOW + 8];
    __shared__ float sred[256];
    __shared__ float sinv[GG];

    const int tid = threadIdx.x;
    const int idx = blockIdx.x;
    const int kv  = idx % NKV;
    const int t   = (idx / NKV) % TT;
    const int b   = idx / (NKV * TT);

    const float scale = 0.08838834764831845f;  // 128^-0.5
    const size_t qrow = (size_t)(b * TT + t) * (NH * HD);

    // load 4 q vectors (scaled)
    #pragma unroll
    for (int i = tid; i < GG * HD; i += 256) {
        const int g = i >> 7, d = i & 127;
        sq[g][d] = Q[qrow + (kv * GG + g) * HD + d] * scale;
    }
    __syncthreads();

    int s0 = t - WINDOW; if (s0 < 0) s0 = 0;
    const int count = t - s0 + 1;        // <= 1025

    const int warp = tid >> 5;           // 0..7
    const int lane = tid & 31;

    float4 qv0 = ((const float4*)sq[0])[lane];
    float4 qv1 = ((const float4*)sq[1])[lane];
    float4 qv2 = ((const float4*)sq[2])[lane];
    float4 qv3 = ((const float4*)sq[3])[lane];

    // Phase 1: warp per key, one K read feeds all 4 heads
    for (int si = warp; si < count; si += 8) {
        const size_t koff = (size_t)(b * TT + s0 + si) * (NKV * HD) + kv * HD;
        const float4 kk = *(const float4*)(K + koff + lane * 4);
        float d0 = qv0.x*kk.x + qv0.y*kk.y + qv0.z*kk.z + qv0.w*kk.w;
        float d1 = qv1.x*kk.x + qv1.y*kk.y + qv1.z*kk.z + qv1.w*kk.w;
        float d2 = qv2.x*kk.x + qv2.y*kk.y + qv2.z*kk.z + qv2.w*kk.w;
        float d3 = qv3.x*kk.x + qv3.y*kk.y + qv3.z*kk.z + qv3.w*kk.w;
        #pragma unroll
        for (int o = 16; o > 0; o >>= 1) {
            d0 += __shfl_xor_sync(0xffffffffu, d0, o);
            d1 += __shfl_xor_sync(0xffffffffu, d1, o);
            d2 += __shfl_xor_sync(0xffffffffu, d2, o);
            d3 += __shfl_xor_sync(0xffffffffu, d3, o);
        }
        if (lane == 0) {
            sl[0][si] = SOFTCAP * tanhf(d0 * (1.0f / SOFTCAP));
            sl[1][si] = SOFTCAP * tanhf(d1 * (1.0f / SOFTCAP));
            sl[2][si] = SOFTCAP * tanhf(d2 * (1.0f / SOFTCAP));
            sl[3][si] = SOFTCAP * tanhf(d3 * (1.0f / SOFTCAP));
        }
    }
    __syncthreads();

    // Phase 2: softmax, 64 threads per head
    {
        const int g  = tid >> 6;
        const int lt = tid & 63;

        float m = -INFINITY;
        for (int si = lt; si < count; si += 64) m = fmaxf(m, sl[g][si]);
        sred[tid] = m;
        __syncthreads();
        #pragma unroll
        for (int s = 32; s > 0; s >>= 1) {
            if (lt < s) sred[tid] = fmaxf(sred[tid], sred[tid + s]);
            __syncthreads();
        }
        m = sred[g * 64];
        __syncthreads();

        float sum = 0.0f;
        for (int si = lt; si < count; si += 64) {
            const float e = __expf(sl[g][si] - m);
            sl[g][si] = e;
            sum += e;
        }
        sred[tid] = sum;
        __syncthreads();
        #pragma unroll
        for (int s = 32; s > 0; s >>= 1) {
            if (lt < s) sred[tid] += sred[tid + s];
            __syncthreads();
        }
        if (lt == 0) sinv[g] = 1.0f / sred[g * 64];
        __syncthreads();
    }

    // Phase 3: PV. 256 threads: d = tid%128, handles heads {gp, gp+2};
    // the V element is shared by the two half-blocks (L1 broadcast).
    {
        const int d  = tid & 127;
        const int gp = tid >> 7;         // 0 or 1
        const float* vbase = V + (size_t)(b * TT + s0) * (NKV * HD) + kv * HD + d;
        const float* p0 = sl[gp];
        const float* p1 = sl[gp + 2];

        float a0 = 0.0f, a1 = 0.0f, b0 = 0.0f, b1 = 0.0f;
        int si = 0;
        for (; si + 2 <= count; si += 2) {
            const float v0 = vbase[(size_t)(si + 0) * (NKV * HD)];
            const float v1 = vbase[(size_t)(si + 1) * (NKV * HD)];
            a0 = fmaf(p0[si + 0], v0, a0);
            b0 = fmaf(p1[si + 0], v0, b0);
            a1 = fmaf(p0[si + 1], v1, a1);
            b1 = fmaf(p1[si + 1], v1, b1);
        }
        if (si < count) {
            const float v0 = vbase[(size_t)si * (NKV * HD)];
            a0 = fmaf(p0[si], v0, a0);
            b0 = fmaf(p1[si], v0, b0);
        }

        E[qrow + (kv * GG + gp) * HD + d]       = (a0 + a1) * sinv[gp];
        E[qrow + (kv * GG + gp + 2) * HD + d]   = (b0 + b1) * sinv[gp + 2];
    }
}

// ---------------------------------------------------------------------------
// Launch
// ---------------------------------------------------------------------------
extern "C" void kernel_launch(void* const* d_in, const int* in_sizes, int n_in,
                              void* d_out, int out_size)
{
    const float* x  = (const float*)d_in[0];
    const float* qk = (const float*)d_in[1];
    const float* kk = (const float*)d_in[2];
    const float* vk = (const float*)d_in[3];
    const float* ok = (const float*)d_in[4];
    float* out = (float*)d_out;

    float *Q, *K, *V, *E;
    cudaGetSymbolAddress((void**)&Q, g_Q);
    cudaGetSymbolAddress((void**)&K, g_K);
    cudaGetSymbolAddress((void**)&V, g_V);
    cudaGetSymbolAddress((void**)&E, g_E);

    sgemm128<<<dim3((NH*HD)/128,  MROWS/128), 256>>>(x, qk, Q, MROWS, NH*HD,  CC);
    sgemm128<<<dim3((NKV*HD)/128, MROWS/128), 256>>>(x, kk, K, MROWS, NKV*HD, CC);
    sgemm128<<<dim3((NKV*HD)/128, MROWS/128), 256>>>(x, vk, V, MROWS, NKV*HD, CC);

    rope_kernel<<<MROWS * NH,  64>>>(Q, NH);
    rope_kernel<<<MROWS * NKV, 64>>>(K, NKV);

    attn_kernel<<<BB * TT * NKV, 256>>>(Q, K, V, E);

    sgemm128<<<dim3(CC/128, MROWS/128), 256>>>(E, ok, out, MROWS, CC, CC);
}

// round 3
// speedup vs baseline: 1.5667x; 1.4853x over previous
#include <cuda_runtime.h>
#include <math.h>
#include <stdint.h>

#define BB 2
#define TT 2048
#define CC 2048
#define NH 16
#define NKV 4
#define HD 128
#define GG 4
#define WINDOW 1024
#define SOFTCAP 50.0f

#define MROWS (BB*TT)   // 4096

__device__ float g_Q[MROWS * (NH*HD)];
__device__ float g_K[MROWS * (NKV*HD)];
__device__ float g_V[MROWS * (NKV*HD)];
__device__ float g_E[MROWS * (NH*HD)];

__device__ __forceinline__ uint32_t f2tf32(float x) {
    uint32_t r;
    asm("cvt.rna.tf32.f32 %0, %1;" : "=r"(r) : "f"(x));
    return r;
}
__device__ __forceinline__ float tanh_fast(float x) {
    float y;
    asm("tanh.approx.f32 %0, %1;" : "=f"(y) : "f"(x));
    return y;
}

// ---------------------------------------------------------------------------
// TF32 tensor-core GEMM: C[M,N] = A[M,K] @ B[K,N], row-major fp32 in/out.
// 128x128 block tile, BK=16, 256 threads = 8 warps (2m x 4n), warp tile 64x32.
// mma.sync.m16n8k8.tf32 with cvt.rna rounding at smem staging.
// Requires: M%128==0, N%128==0, K%16==0.
// ---------------------------------------------------------------------------
__global__ __launch_bounds__(256) void gemm_tf32(
    const float* __restrict__ A, const float* __restrict__ B,
    float* __restrict__ C, int M, int N, int Kd)
{
    __shared__ float As[16][132];   // [k][m] (A transposed), tf32 bits
    __shared__ float Bs[16][132];   // [k][n], tf32 bits

    const int tid  = threadIdx.x;
    const int lane = tid & 31;
    const int wid  = tid >> 5;
    const int wm   = wid >> 2;      // 0..1
    const int wn   = wid & 3;       // 0..3
    const int grp  = lane >> 2;     // 0..7
    const int tig  = lane & 3;      // 0..3

    const int row0 = blockIdx.y * 128;
    const int col0 = blockIdx.x * 128;

    // A loader: thread -> rows (r0, r0+64), k-float4 kc
    const int ar = tid >> 2;        // 0..63
    const int kc = tid & 3;         // 0..3
    // B loader: thread -> k rows (kr, kr+8), n-float4 n4
    const int n4 = tid & 31;        // 0..31
    const int kr = tid >> 5;        // 0..7

    const float* Ap0 = A + (size_t)(row0 + ar)      * Kd + kc * 4;
    const float* Ap1 = A + (size_t)(row0 + ar + 64) * Kd + kc * 4;
    const float* Bp0 = B + (size_t)kr       * N + col0 + n4 * 4;
    const float* Bp1 = B + (size_t)(kr + 8) * N + col0 + n4 * 4;

    float acc[4][4][4];
    #pragma unroll
    for (int i = 0; i < 4; i++)
        #pragma unroll
        for (int j = 0; j < 4; j++)
            #pragma unroll
            for (int c = 0; c < 4; c++) acc[i][j][c] = 0.0f;

    float4 ga0 = *(const float4*)Ap0;
    float4 ga1 = *(const float4*)Ap1;
    float4 gb0 = *(const float4*)Bp0;
    float4 gb1 = *(const float4*)Bp1;

    const int nIter = Kd >> 4;
    for (int it = 0; it < nIter; it++) {
        // stage with tf32 rounding
        As[kc*4 + 0][ar]      = __uint_as_float(f2tf32(ga0.x));
        As[kc*4 + 1][ar]      = __uint_as_float(f2tf32(ga0.y));
        As[kc*4 + 2][ar]      = __uint_as_float(f2tf32(ga0.z));
        As[kc*4 + 3][ar]      = __uint_as_float(f2tf32(ga0.w));
        As[kc*4 + 0][ar + 64] = __uint_as_float(f2tf32(ga1.x));
        As[kc*4 + 1][ar + 64] = __uint_as_float(f2tf32(ga1.y));
        As[kc*4 + 2][ar + 64] = __uint_as_float(f2tf32(ga1.z));
        As[kc*4 + 3][ar + 64] = __uint_as_float(f2tf32(ga1.w));

        float4 tb;
        tb.x = __uint_as_float(f2tf32(gb0.x));
        tb.y = __uint_as_float(f2tf32(gb0.y));
        tb.z = __uint_as_float(f2tf32(gb0.z));
        tb.w = __uint_as_float(f2tf32(gb0.w));
        *(float4*)&Bs[kr][n4*4] = tb;
        tb.x = __uint_as_float(f2tf32(gb1.x));
        tb.y = __uint_as_float(f2tf32(gb1.y));
        tb.z = __uint_as_float(f2tf32(gb1.z));
        tb.w = __uint_as_float(f2tf32(gb1.w));
        *(float4*)&Bs[kr + 8][n4*4] = tb;

        __syncthreads();

        if (it + 1 < nIter) {
            ga0 = *(const float4*)(Ap0 + (it + 1) * 16);
            ga1 = *(const float4*)(Ap1 + (it + 1) * 16);
            gb0 = *(const float4*)(Bp0 + (size_t)(it + 1) * 16 * N);
            gb1 = *(const float4*)(Bp1 + (size_t)(it + 1) * 16 * N);
        }

        #pragma unroll
        for (int kk = 0; kk < 16; kk += 8) {
            uint32_t af[4][4], bf[4][2];
            #pragma unroll
            for (int i = 0; i < 4; i++) {
                const int m0 = wm*64 + i*16 + grp;
                af[i][0] = __float_as_uint(As[kk + tig]    [m0]);
                af[i][1] = __float_as_uint(As[kk + tig]    [m0 + 8]);
                af[i][2] = __float_as_uint(As[kk + tig + 4][m0]);
                af[i][3] = __float_as_uint(As[kk + tig + 4][m0 + 8]);
            }
            #pragma unroll
            for (int j = 0; j < 4; j++) {
                const int n0 = wn*32 + j*8 + grp;
                bf[j][0] = __float_as_uint(Bs[kk + tig]    [n0]);
                bf[j][1] = __float_as_uint(Bs[kk + tig + 4][n0]);
            }
            #pragma unroll
            for (int i = 0; i < 4; i++)
                #pragma unroll
                for (int j = 0; j < 4; j++) {
                    asm volatile(
                        "mma.sync.aligned.m16n8k8.row.col.f32.tf32.tf32.f32 "
                        "{%0,%1,%2,%3}, {%4,%5,%6,%7}, {%8,%9}, {%0,%1,%2,%3};"
                        : "+f"(acc[i][j][0]), "+f"(acc[i][j][1]),
                          "+f"(acc[i][j][2]), "+f"(acc[i][j][3])
                        : "r"(af[i][0]), "r"(af[i][1]), "r"(af[i][2]), "r"(af[i][3]),
                          "r"(bf[j][0]), "r"(bf[j][1]));
                }
        }
        __syncthreads();
    }

    // epilogue
    #pragma unroll
    for (int i = 0; i < 4; i++) {
        const int row = row0 + wm*64 + i*16 + grp;
        #pragma unroll
        for (int j = 0; j < 4; j++) {
            const int col = col0 + wn*32 + j*8 + tig*2;
            float2 v0 = make_float2(acc[i][j][0], acc[i][j][1]);
            float2 v1 = make_float2(acc[i][j][2], acc[i][j][3]);
            *(float2*)(C + (size_t)row * N + col)       = v0;
            *(float2*)(C + (size_t)(row + 8) * N + col) = v1;
        }
    }
}

// ---------------------------------------------------------------------------
// RoPE
// ---------------------------------------------------------------------------
__global__ void rope_kernel(float* data, int nheads)
{
    const int idx = blockIdx.x;
    const int h   = idx % nheads;
    const int row = idx / nheads;
    const int t   = row % TT;

    float* p = data + (size_t)row * nheads * HD + h * HD;
    const int i = threadIdx.x;           // 0..63

    // theta^{-i/64} = 2^{-i/64 * log2(10000)}
    const float a = (float)t * exp2f(-(float)i * (13.287712379549449f / 64.0f));
    float c, s;
    __sincosf(a, &s, &c);

    const float x1 = p[i];
    const float x2 = p[i + 64];
    p[i]      = x1 * c - x2 * s;
    p[i + 64] = x2 * c + x1 * s;
}

// ---------------------------------------------------------------------------
// Attention: one block per (b, t, kv-group). 256 threads.
// ---------------------------------------------------------------------------
__global__ __launch_bounds__(256) void attn_kernel(
    const float* __restrict__ Q, const float* __restrict__ K,
    const float* __restrict__ V, float* __restrict__ E)
{
    __shared__ float sq[GG][HD];
    __shared__ float sl[GG][WINDOW + 8];
    __shared__ float sred[256];
    __shared__ float sinv[GG];

    const int tid = threadIdx.x;
    const int idx = blockIdx.x;
    const int kv  = idx % NKV;
    const int t   = (idx / NKV) % TT;
    const int b   = idx / (NKV * TT);

    const float scale = 0.08838834764831845f;  // 128^-0.5
    const size_t qrow = (size_t)(b * TT + t) * (NH * HD);

    #pragma unroll
    for (int i = tid; i < GG * HD; i += 256) {
        const int g = i >> 7, d = i & 127;
        sq[g][d] = Q[qrow + (kv * GG + g) * HD + d] * scale;
    }
    __syncthreads();

    int s0 = t - WINDOW; if (s0 < 0) s0 = 0;
    const int count = t - s0 + 1;        // <= 1025

    const int warp = tid >> 5;
    const int lane = tid & 31;

    float4 qv0 = ((const float4*)sq[0])[lane];
    float4 qv1 = ((const float4*)sq[1])[lane];
    float4 qv2 = ((const float4*)sq[2])[lane];
    float4 qv3 = ((const float4*)sq[3])[lane];

    for (int si = warp; si < count; si += 8) {
        const size_t koff = (size_t)(b * TT + s0 + si) * (NKV * HD) + kv * HD;
        const float4 kk = *(const float4*)(K + koff + lane * 4);
        float d0 = qv0.x*kk.x + qv0.y*kk.y + qv0.z*kk.z + qv0.w*kk.w;
        float d1 = qv1.x*kk.x + qv1.y*kk.y + qv1.z*kk.z + qv1.w*kk.w;
        float d2 = qv2.x*kk.x + qv2.y*kk.y + qv2.z*kk.z + qv2.w*kk.w;
        float d3 = qv3.x*kk.x + qv3.y*kk.y + qv3.z*kk.z + qv3.w*kk.w;
        #pragma unroll
        for (int o = 16; o > 0; o >>= 1) {
            d0 += __shfl_xor_sync(0xffffffffu, d0, o);
            d1 += __shfl_xor_sync(0xffffffffu, d1, o);
            d2 += __shfl_xor_sync(0xffffffffu, d2, o);
            d3 += __shfl_xor_sync(0xffffffffu, d3, o);
        }
        if (lane == 0) {
            sl[0][si] = SOFTCAP * tanh_fast(d0 * (1.0f / SOFTCAP));
            sl[1][si] = SOFTCAP * tanh_fast(d1 * (1.0f / SOFTCAP));
            sl[2][si] = SOFTCAP * tanh_fast(d2 * (1.0f / SOFTCAP));
            sl[3][si] = SOFTCAP * tanh_fast(d3 * (1.0f / SOFTCAP));
        }
    }
    __syncthreads();

    {
        const int g  = tid >> 6;
        const int lt = tid & 63;

        float m = -INFINITY;
        for (int si = lt; si < count; si += 64) m = fmaxf(m, sl[g][si]);
        sred[tid] = m;
        __syncthreads();
        #pragma unroll
        for (int s = 32; s > 0; s >>= 1) {
            if (lt < s) sred[tid] = fmaxf(sred[tid], sred[tid + s]);
            __syncthreads();
        }
        m = sred[g * 64];
        __syncthreads();

        float sum = 0.0f;
        for (int si = lt; si < count; si += 64) {
            const float e = __expf(sl[g][si] - m);
            sl[g][si] = e;
            sum += e;
        }
        sred[tid] = sum;
        __syncthreads();
        #pragma unroll
        for (int s = 32; s > 0; s >>= 1) {
            if (lt < s) sred[tid] += sred[tid + s];
            __syncthreads();
        }
        if (lt == 0) sinv[g] = 1.0f / sred[g * 64];
        __syncthreads();
    }

    {
        const int d  = tid & 127;
        const int gp = tid >> 7;         // 0 or 1
        const float* vbase = V + (size_t)(b * TT + s0) * (NKV * HD) + kv * HD + d;
        const float* p0 = sl[gp];
        const float* p1 = sl[gp + 2];

        float a0 = 0.0f, a1 = 0.0f, b0 = 0.0f, b1 = 0.0f;
        int si = 0;
        for (; si + 2 <= count; si += 2) {
            const float v0 = vbase[(size_t)(si + 0) * (NKV * HD)];
            const float v1 = vbase[(size_t)(si + 1) * (NKV * HD)];
            a0 = fmaf(p0[si + 0], v0, a0);
            b0 = fmaf(p1[si + 0], v0, b0);
            a1 = fmaf(p0[si + 1], v1, a1);
            b1 = fmaf(p1[si + 1], v1, b1);
        }
        if (si < count) {
            const float v0 = vbase[(size_t)si * (NKV * HD)];
            a0 = fmaf(p0[si], v0, a0);
            b0 = fmaf(p1[si], v0, b0);
        }

        E[qrow + (kv * GG + gp) * HD + d]     = (a0 + a1) * sinv[gp];
        E[qrow + (kv * GG + gp + 2) * HD + d] = (b0 + b1) * sinv[gp + 2];
    }
}

// ---------------------------------------------------------------------------
// Launch
// ---------------------------------------------------------------------------
extern "C" void kernel_launch(void* const* d_in, const int* in_sizes, int n_in,
                              void* d_out, int out_size)
{
    const float* x  = (const float*)d_in[0];
    const float* qk = (const float*)d_in[1];
    const float* kk = (const float*)d_in[2];
    const float* vk = (const float*)d_in[3];
    const float* ok = (const float*)d_in[4];
    float* out = (float*)d_out;

    float *Q, *K, *V, *E;
    cudaGetSymbolAddress((void**)&Q, g_Q);
    cudaGetSymbolAddress((void**)&K, g_K);
    cudaGetSymbolAddress((void**)&V, g_V);
    cudaGetSymbolAddress((void**)&E, g_E);

    gemm_tf32<<<dim3((NH*HD)/128,  MROWS/128), 256>>>(x, qk, Q, MROWS, NH*HD,  CC);
    gemm_tf32<<<dim3((NKV*HD)/128, MROWS/128), 256>>>(x, kk, K, MROWS, NKV*HD, CC);
    gemm_tf32<<<dim3((NKV*HD)/128, MROWS/128), 256>>>(x, vk, V, MROWS, NKV*HD, CC);

    rope_kernel<<<MROWS * NH,  64>>>(Q, NH);
    rope_kernel<<<MROWS * NKV, 64>>>(K, NKV);

    attn_kernel<<<BB * TT * NKV, 256>>>(Q, K, V, E);

    gemm_tf32<<<dim3(CC/128, MROWS/128), 256>>>(E, ok, out, MROWS, CC, CC);
}

// round 6
// speedup vs baseline: 2.6262x; 1.6763x over previous
#include <cuda_runtime.h>
#include <math.h>
#include <stdint.h>

#define BB 2
#define TT 2048
#define CC 2048
#define NH 16
#define NKV 4
#define HD 128
#define GG 4
#define WINDOW 1024
#define SOFTCAP 50.0f
#define TQ 64
#define TK 32

#define MROWS (BB*TT)   // 4096

__device__ float g_Q[MROWS * (NH*HD)];
__device__ float g_K[MROWS * (NKV*HD)];
__device__ float g_V[MROWS * (NKV*HD)];
__device__ float g_E[MROWS * (NH*HD)];

__device__ __forceinline__ uint32_t f2tf32(float x) {
    uint32_t r;
    asm("cvt.rna.tf32.f32 %0, %1;" : "=r"(r) : "f"(x));
    return r;
}
__device__ __forceinline__ float tanh_fast(float x) {
    float y;
    asm("tanh.approx.f32 %0, %1;" : "=f"(y) : "f"(x));
    return y;
}
__device__ __forceinline__ unsigned long long fma2(
    unsigned long long a, unsigned long long b, unsigned long long c) {
    unsigned long long d;
    asm("fma.rn.f32x2 %0, %1, %2, %3;" : "=l"(d) : "l"(a), "l"(b), "l"(c));
    return d;
}
__device__ __forceinline__ unsigned long long pack2(float lo, float hi) {
    unsigned long long r;
    asm("mov.b64 %0, {%1, %2};" : "=l"(r) : "f"(lo), "f"(hi));
    return r;
}
__device__ __forceinline__ void unpack2(unsigned long long v, float& lo, float& hi) {
    asm("mov.b64 {%0, %1}, %2;" : "=f"(lo), "=f"(hi) : "l"(v));
}

// ---------------------------------------------------------------------------
// TF32 tensor-core GEMM (unchanged from round 3)
// ---------------------------------------------------------------------------
__global__ __launch_bounds__(256) void gemm_tf32(
    const float* __restrict__ A, const float* __restrict__ B,
    float* __restrict__ C, int M, int N, int Kd)
{
    __shared__ float As[16][132];
    __shared__ float Bs[16][132];

    const int tid  = threadIdx.x;
    const int lane = tid & 31;
    const int wid  = tid >> 5;
    const int wm   = wid >> 2;
    const int wn   = wid & 3;
    const int grp  = lane >> 2;
    const int tig  = lane & 3;

    const int row0 = blockIdx.y * 128;
    const int col0 = blockIdx.x * 128;

    const int ar = tid >> 2;
    const int kc = tid & 3;
    const int n4 = tid & 31;
    const int kr = tid >> 5;

    const float* Ap0 = A + (size_t)(row0 + ar)      * Kd + kc * 4;
    const float* Ap1 = A + (size_t)(row0 + ar + 64) * Kd + kc * 4;
    const float* Bp0 = B + (size_t)kr       * N + col0 + n4 * 4;
    const float* Bp1 = B + (size_t)(kr + 8) * N + col0 + n4 * 4;

    float acc[4][4][4];
    #pragma unroll
    for (int i = 0; i < 4; i++)
        #pragma unroll
        for (int j = 0; j < 4; j++)
            #pragma unroll
            for (int c = 0; c < 4; c++) acc[i][j][c] = 0.0f;

    float4 ga0 = *(const float4*)Ap0;
    float4 ga1 = *(const float4*)Ap1;
    float4 gb0 = *(const float4*)Bp0;
    float4 gb1 = *(const float4*)Bp1;

    const int nIter = Kd >> 4;
    for (int it = 0; it < nIter; it++) {
        As[kc*4 + 0][ar]      = __uint_as_float(f2tf32(ga0.x));
        As[kc*4 + 1][ar]      = __uint_as_float(f2tf32(ga0.y));
        As[kc*4 + 2][ar]      = __uint_as_float(f2tf32(ga0.z));
        As[kc*4 + 3][ar]      = __uint_as_float(f2tf32(ga0.w));
        As[kc*4 + 0][ar + 64] = __uint_as_float(f2tf32(ga1.x));
        As[kc*4 + 1][ar + 64] = __uint_as_float(f2tf32(ga1.y));
        As[kc*4 + 2][ar + 64] = __uint_as_float(f2tf32(ga1.z));
        As[kc*4 + 3][ar + 64] = __uint_as_float(f2tf32(ga1.w));

        float4 tb;
        tb.x = __uint_as_float(f2tf32(gb0.x));
        tb.y = __uint_as_float(f2tf32(gb0.y));
        tb.z = __uint_as_float(f2tf32(gb0.z));
        tb.w = __uint_as_float(f2tf32(gb0.w));
        *(float4*)&Bs[kr][n4*4] = tb;
        tb.x = __uint_as_float(f2tf32(gb1.x));
        tb.y = __uint_as_float(f2tf32(gb1.y));
        tb.z = __uint_as_float(f2tf32(gb1.z));
        tb.w = __uint_as_float(f2tf32(gb1.w));
        *(float4*)&Bs[kr + 8][n4*4] = tb;

        __syncthreads();

        if (it + 1 < nIter) {
            ga0 = *(const float4*)(Ap0 + (it + 1) * 16);
            ga1 = *(const float4*)(Ap1 + (it + 1) * 16);
            gb0 = *(const float4*)(Bp0 + (size_t)(it + 1) * 16 * N);
            gb1 = *(const float4*)(Bp1 + (size_t)(it + 1) * 16 * N);
        }

        #pragma unroll
        for (int kk = 0; kk < 16; kk += 8) {
            uint32_t af[4][4], bf[4][2];
            #pragma unroll
            for (int i = 0; i < 4; i++) {
                const int m0 = wm*64 + i*16 + grp;
                af[i][0] = __float_as_uint(As[kk + tig]    [m0]);
                af[i][1] = __float_as_uint(As[kk + tig]    [m0 + 8]);
                af[i][2] = __float_as_uint(As[kk + tig + 4][m0]);
                af[i][3] = __float_as_uint(As[kk + tig + 4][m0 + 8]);
            }
            #pragma unroll
            for (int j = 0; j < 4; j++) {
                const int n0 = wn*32 + j*8 + grp;
                bf[j][0] = __float_as_uint(Bs[kk + tig]    [n0]);
                bf[j][1] = __float_as_uint(Bs[kk + tig + 4][n0]);
            }
            #pragma unroll
            for (int i = 0; i < 4; i++)
                #pragma unroll
                for (int j = 0; j < 4; j++) {
                    asm volatile(
                        "mma.sync.aligned.m16n8k8.row.col.f32.tf32.tf32.f32 "
                        "{%0,%1,%2,%3}, {%4,%5,%6,%7}, {%8,%9}, {%0,%1,%2,%3};"
                        : "+f"(acc[i][j][0]), "+f"(acc[i][j][1]),
                          "+f"(acc[i][j][2]), "+f"(acc[i][j][3])
                        : "r"(af[i][0]), "r"(af[i][1]), "r"(af[i][2]), "r"(af[i][3]),
                          "r"(bf[j][0]), "r"(bf[j][1]));
                }
        }
        __syncthreads();
    }

    #pragma unroll
    for (int i = 0; i < 4; i++) {
        const int row = row0 + wm*64 + i*16 + grp;
        #pragma unroll
        for (int j = 0; j < 4; j++) {
            const int col = col0 + wn*32 + j*8 + tig*2;
            *(float2*)(C + (size_t)row * N + col)       = make_float2(acc[i][j][0], acc[i][j][1]);
            *(float2*)(C + (size_t)(row + 8) * N + col) = make_float2(acc[i][j][2], acc[i][j][3]);
        }
    }
}

// ---------------------------------------------------------------------------
// RoPE
// ---------------------------------------------------------------------------
__global__ void rope_kernel(float* data, int nheads)
{
    const int idx = blockIdx.x;
    const int h   = idx % nheads;
    const int row = idx / nheads;
    const int t   = row % TT;

    float* p = data + (size_t)row * nheads * HD + h * HD;
    const int i = threadIdx.x;           // 0..63

    const float a = (float)t * exp2f(-(float)i * (13.287712379549449f / 64.0f));
    float c, s;
    __sincosf(a, &s, &c);

    const float x1 = p[i];
    const float x2 = p[i + 64];
    p[i]      = x1 * c - x2 * s;
    p[i + 64] = x2 * c + x1 * s;
}

// ---------------------------------------------------------------------------
// Flash-tiled attention.
// Block = (q-tile of 64, head, batch). 256 threads = 8 warps.
// QK^T: tf32 mma, warps arranged 4(m) x 2(n); warp tile 16q x 16k.
// Softcap bounds logits to [-50,50] -> exp without max subtraction.
// PV: fp32x2 packed FMA from P,V in smem; thread = (query, 32 dims).
// ---------------------------------------------------------------------------
struct AttnSmem {
    float Q[TQ][132];        // tf32-rounded, pre-scaled
    float K[TK][132];        // tf32-rounded
    float V[TK][132];        // fp32
    float P[TQ][36];         // probs for current key tile
    float rowsum[2][TQ];     // per-wn partial row sums
};

__global__ __launch_bounds__(256, 2) void attn_kernel(
    const float* __restrict__ Q, const float* __restrict__ K,
    const float* __restrict__ V, float* __restrict__ E)
{
    extern __shared__ float smem_raw[];
    AttnSmem& sm = *reinterpret_cast<AttnSmem*>(smem_raw);

    const int tid  = threadIdx.x;
    const int qt   = blockIdx.x;
    const int head = blockIdx.y;
    const int b    = blockIdx.z;
    const int kv   = head >> 2;
    const int q0   = qt * TQ;

    const float scale = 0.08838834764831845f;  // 128^-0.5

    // ---- stage Q tile (scaled, tf32) : 64x128 = 2048 float4
    for (int i = tid; i < 2048; i += 256) {
        const int r = i >> 5, c4 = i & 31;
        float4 v = *(const float4*)(Q + (size_t)(b*TT + q0 + r) * (NH*HD) + head*HD + c4*4);
        float4 tv;
        tv.x = __uint_as_float(f2tf32(v.x * scale));
        tv.y = __uint_as_float(f2tf32(v.y * scale));
        tv.z = __uint_as_float(f2tf32(v.z * scale));
        tv.w = __uint_as_float(f2tf32(v.w * scale));
        *(float4*)&sm.Q[r][c4*4] = tv;
    }

    // warp coords for mma
    const int lane = tid & 31, wid = tid >> 5;
    const int wm = wid >> 1, wn = wid & 1;
    const int grp = lane >> 2, quad = lane & 3;
    const int r0 = wm*16 + grp;
    const int t_lo = q0 + r0;
    const int t_hi = t_lo + 8;

    // PV thread mapping
    const int pq   = tid >> 2;          // query 0..63
    const int toff = (tid & 3) * 2;     // dim offset 0,2,4,6

    int s_begin = q0 - WINDOW; if (s_begin < 0) s_begin = 0;
    const int s_end  = q0 + TQ - 1;
    const int ntiles = (s_end - s_begin) / TK + 1;

    float lsum0 = 0.0f, lsum1 = 0.0f;
    unsigned long long acc[16];
    #pragma unroll
    for (int i = 0; i < 16; i++) acc[i] = 0ULL;

    for (int tile = 0; tile < ntiles; tile++) {
        const int s0 = s_begin + tile * TK;

        __syncthreads();   // previous tile's P/V fully consumed (and Q staged, tile 0)

        // ---- stage K (tf32) and V tiles: 2 * 32*128 floats = 2048 float4
        for (int i = tid; i < 2048; i += 256) {
            const int which = i >> 10;          // 0=K, 1=V
            const int j = i & 1023;
            const int r = j >> 5, c4 = j & 31;
            int srow = s0 + r; if (srow > TT-1) srow = TT-1;
            const float* src = which ? V : K;
            float4 v = *(const float4*)(src + (size_t)(b*TT + srow) * (NKV*HD) + kv*HD + c4*4);
            if (which) {
                *(float4*)&sm.V[r][c4*4] = v;
            } else {
                float4 tv;
                tv.x = __uint_as_float(f2tf32(v.x));
                tv.y = __uint_as_float(f2tf32(v.y));
                tv.z = __uint_as_float(f2tf32(v.z));
                tv.w = __uint_as_float(f2tf32(v.w));
                *(float4*)&sm.K[r][c4*4] = tv;
            }
        }
        __syncthreads();

        // ---- S = Q K^T (warp tile 16x16: 2 n-steps, 16 k-steps)
        float c[2][4];
        #pragma unroll
        for (int n = 0; n < 2; n++)
            #pragma unroll
            for (int i = 0; i < 4; i++) c[n][i] = 0.0f;

        #pragma unroll
        for (int ks = 0; ks < 16; ks++) {
            const uint32_t a0 = __float_as_uint(sm.Q[r0]    [ks*8 + quad]);
            const uint32_t a1 = __float_as_uint(sm.Q[r0 + 8][ks*8 + quad]);
            const uint32_t a2 = __float_as_uint(sm.Q[r0]    [ks*8 + quad + 4]);
            const uint32_t a3 = __float_as_uint(sm.Q[r0 + 8][ks*8 + quad + 4]);
            #pragma unroll
            for (int n = 0; n < 2; n++) {
                const int key = wn*16 + n*8 + grp;
                const uint32_t b0 = __float_as_uint(sm.K[key][ks*8 + quad]);
                const uint32_t b1 = __float_as_uint(sm.K[key][ks*8 + quad + 4]);
                asm volatile(
                    "mma.sync.aligned.m16n8k8.row.col.f32.tf32.tf32.f32 "
                    "{%0,%1,%2,%3}, {%4,%5,%6,%7}, {%8,%9}, {%0,%1,%2,%3};"
                    : "+f"(c[n][0]), "+f"(c[n][1]), "+f"(c[n][2]), "+f"(c[n][3])
                    : "r"(a0), "r"(a1), "r"(a2), "r"(a3), "r"(b0), "r"(b1));
            }
        }

        // ---- softcap + mask + exp, store P, accumulate row sums
        #pragma unroll
        for (int n = 0; n < 2; n++) {
            const int col = wn*16 + n*8 + 2*quad;
            const int sg0 = s0 + col, sg1 = sg0 + 1;

            float p00 = __expf(SOFTCAP * tanh_fast(c[n][0] * (1.0f/SOFTCAP)));
            float p01 = __expf(SOFTCAP * tanh_fast(c[n][1] * (1.0f/SOFTCAP)));
            float p10 = __expf(SOFTCAP * tanh_fast(c[n][2] * (1.0f/SOFTCAP)));
            float p11 = __expf(SOFTCAP * tanh_fast(c[n][3] * (1.0f/SOFTCAP)));

            p00 = (sg0 <= t_lo && sg0 + WINDOW >= t_lo) ? p00 : 0.0f;
            p01 = (sg1 <= t_lo && sg1 + WINDOW >= t_lo) ? p01 : 0.0f;
            p10 = (sg0 <= t_hi && sg0 + WINDOW >= t_hi) ? p10 : 0.0f;
            p11 = (sg1 <= t_hi && sg1 + WINDOW >= t_hi) ? p11 : 0.0f;

            *(float2*)&sm.P[r0]    [col] = make_float2(p00, p01);
            *(float2*)&sm.P[r0 + 8][col] = make_float2(p10, p11);
            lsum0 += p00 + p01;
            lsum1 += p10 + p11;
        }
        __syncthreads();

        // ---- PV: thread accumulates 32 dims (as 16 f32x2) for query pq
        const float* Prow = sm.P[pq];
        #pragma unroll 4
        for (int s = 0; s < TK; s += 2) {
            const float2 pp = *(const float2*)&Prow[s];
            const unsigned long long pk0 = pack2(pp.x, pp.x);
            const unsigned long long pk1 = pack2(pp.y, pp.y);
            #pragma unroll
            for (int i = 0; i < 16; i++) {
                const unsigned long long v0 =
                    *(const unsigned long long*)&sm.V[s][toff + 8*i];
                acc[i] = fma2(pk0, v0, acc[i]);
            }
            #pragma unroll
            for (int i = 0; i < 16; i++) {
                const unsigned long long v1 =
                    *(const unsigned long long*)&sm.V[s + 1][toff + 8*i];
                acc[i] = fma2(pk1, v1, acc[i]);
            }
        }
    }

    // ---- reduce row sums: over quad (shfl), then over wn (smem)
    lsum0 += __shfl_xor_sync(0xffffffffu, lsum0, 1);
    lsum0 += __shfl_xor_sync(0xffffffffu, lsum0, 2);
    lsum1 += __shfl_xor_sync(0xffffffffu, lsum1, 1);
    lsum1 += __shfl_xor_sync(0xffffffffu, lsum1, 2);
    __syncthreads();   // PV done reading P/V before rowsum reuse? (distinct arrays, but order anyway)
    if (quad == 0) {
        sm.rowsum[wn][r0]     = lsum0;
        sm.rowsum[wn][r0 + 8] = lsum1;
    }
    __syncthreads();

    const float inv = 1.0f / (sm.rowsum[0][pq] + sm.rowsum[1][pq]);
    float* dst = E + (size_t)(b*TT + q0 + pq) * (NH*HD) + head*HD;
    #pragma unroll
    for (int i = 0; i < 16; i++) {
        float lo, hi;
        unpack2(acc[i], lo, hi);
        *(float2*)&dst[toff + 8*i] = make_float2(lo * inv, hi * inv);
    }
}

// ---------------------------------------------------------------------------
// Launch
// ---------------------------------------------------------------------------
extern "C" void kernel_launch(void* const* d_in, const int* in_sizes, int n_in,
                              void* d_out, int out_size)
{
    const float* x  = (const float*)d_in[0];
    const float* qk = (const float*)d_in[1];
    const float* kk = (const float*)d_in[2];
    const float* vk = (const float*)d_in[3];
    const float* ok = (const float*)d_in[4];
    float* out = (float*)d_out;

    float *Q, *K, *V, *E;
    cudaGetSymbolAddress((void**)&Q, g_Q);
    cudaGetSymbolAddress((void**)&K, g_K);
    cudaGetSymbolAddress((void**)&V, g_V);
    cudaGetSymbolAddress((void**)&E, g_E);

    const int attn_smem = (int)sizeof(AttnSmem);
    cudaFuncSetAttribute(attn_kernel,
                         cudaFuncAttributeMaxDynamicSharedMemorySize, attn_smem);

    gemm_tf32<<<dim3((NH*HD)/128,  MROWS/128), 256>>>(x, qk, Q, MROWS, NH*HD,  CC);
    gemm_tf32<<<dim3((NKV*HD)/128, MROWS/128), 256>>>(x, kk, K, MROWS, NKV*HD, CC);
    gemm_tf32<<<dim3((NKV*HD)/128, MROWS/128), 256>>>(x, vk, V, MROWS, NKV*HD, CC);

    rope_kernel<<<MROWS * NH,  64>>>(Q, NH);
    rope_kernel<<<MROWS * NKV, 64>>>(K, NKV);

    attn_kernel<<<dim3(TT/TQ, NH, BB), 256, attn_smem>>>(Q, K, V, E);

    gemm_tf32<<<dim3(CC/128, MROWS/128), 256>>>(E, ok, out, MROWS, CC, CC);
}